// round 14
// baseline (speedup 1.0000x reference)
#include <cuda_runtime.h>
#include <cstdint>

// Problem constants
#define BATCH   4
#define NSEQ    2048
#define DIM     512
#define HEADS   8
#define DHEAD   64
#define INNER   512          // HEADS*DHEAD
#define QKVN    1536         // 3*INNER
#define SCALE   0.125f       // 64^-0.5
#define THRESH  0.01f
#define NROWS   ((size_t)BATCH * HEADS * NSEQ)   // 65536 attention rows
#define MAXC    1664   // hard bound: <=100 candidates/tile (each >1% of tile sum) * 16 tiles

// Scratch (device globals: allocation-free per harness rules)
__device__ float  g_qkv[(size_t)BATCH * NSEQ * QKVN];                // 50.3 MB
__device__ float  g_ctx[(size_t)BATCH * NSEQ * INNER];               // 16.8 MB
__device__ float2 g_part[NROWS * 16];                                // (max, sumexp) per (row, jtile)
__device__ int    g_ccnt[NROWS];                                     // candidate counts
__device__ int2   g_cand[NROWS * MAXC];                              // (col, z as bits) ~873 MB

// ---------------------------------------------------------------------------
// fp32 SGEMM, double-buffered (decision-critical): C = A @ B + bias
// 128x128 tile, BK=8, 256 threads, 8x8 per thread. (validated R7)
// ---------------------------------------------------------------------------
__global__ __launch_bounds__(256) void sgemm_bias_kernel(
    const float* __restrict__ A, const float* __restrict__ Bm,
    const float* __restrict__ bias, float* __restrict__ C,
    int M, int Nn, int K)
{
    __shared__ float As[2][8][128];
    __shared__ float Bs[2][8][128];
    const int tid = threadIdx.x;
    const int bx = blockIdx.x, by = blockIdx.y;
    const int tx = tid & 15, ty = tid >> 4;
    const int la_r = tid >> 1, la_c = (tid & 1) * 4;
    const int lb_r = tid >> 5, lb_c = (tid & 31) * 4;

    const float* Ap = A + (size_t)(by * 128 + la_r) * K + la_c;
    const float* Bp = Bm + (size_t)lb_r * Nn + bx * 128 + lb_c;

    float4 a4 = *(const float4*)Ap;
    float4 b4 = *(const float4*)Bp;
    As[0][la_c + 0][la_r] = a4.x; As[0][la_c + 1][la_r] = a4.y;
    As[0][la_c + 2][la_r] = a4.z; As[0][la_c + 3][la_r] = a4.w;
    *(float4*)&Bs[0][lb_r][lb_c] = b4;
    __syncthreads();

    float acc[8][8] = {};
    int cur = 0;
    for (int k0 = 0; k0 < K; k0 += 8) {
        const bool nxt = (k0 + 8 < K);
        if (nxt) {
            a4 = *(const float4*)(Ap + k0 + 8);
            b4 = *(const float4*)(Bp + (size_t)(k0 + 8) * Nn);
        }
        #pragma unroll
        for (int kk = 0; kk < 8; kk++) {
            float ar[8], br[8];
            #pragma unroll
            for (int i = 0; i < 8; i++) ar[i] = As[cur][kk][ty * 8 + i];
            #pragma unroll
            for (int j = 0; j < 8; j++) br[j] = Bs[cur][kk][tx * 8 + j];
            #pragma unroll
            for (int i = 0; i < 8; i++)
                #pragma unroll
                for (int j = 0; j < 8; j++)
                    acc[i][j] = fmaf(ar[i], br[j], acc[i][j]);
        }
        if (nxt) {
            int b2 = cur ^ 1;
            As[b2][la_c + 0][la_r] = a4.x; As[b2][la_c + 1][la_r] = a4.y;
            As[b2][la_c + 2][la_r] = a4.z; As[b2][la_c + 3][la_r] = a4.w;
            *(float4*)&Bs[b2][lb_r][lb_c] = b4;
            __syncthreads();
            cur = b2;
        }
    }

    float bv[8];
    #pragma unroll
    for (int j = 0; j < 8; j++) bv[j] = bias ? bias[bx * 128 + tx * 8 + j] : 0.0f;
    #pragma unroll
    for (int i = 0; i < 8; i++) {
        size_t roff = (size_t)(by * 128 + ty * 8 + i) * Nn + bx * 128 + tx * 8;
        float4 o0 = make_float4(acc[i][0] + bv[0], acc[i][1] + bv[1],
                                acc[i][2] + bv[2], acc[i][3] + bv[3]);
        float4 o1 = make_float4(acc[i][4] + bv[4], acc[i][5] + bv[5],
                                acc[i][6] + bv[6], acc[i][7] + bv[7]);
        *(float4*)(C + roff)     = o0;
        *(float4*)(C + roff + 4) = o1;
    }
}

// ---------------------------------------------------------------------------
// fp32 scores (decision-critical), double-buffered. NO score tensor output.
// Epilogue: per-(row, jtile) stats (m, sumexp) -> g_part, and candidate push
// with per-tile cutoff zcut = m_t + ln(THRESH*s_t) - 1e-3 (provable superset
// of global survivors; <=100/tile by construction so MAXC=1664 never
// overflows). Push is warp-aggregated: one atomicAdd per (row, tile).
// ---------------------------------------------------------------------------
__global__ __launch_bounds__(256) void scores_kernel()
{
    __shared__ float Qs[2][8][128];
    __shared__ float Ks[2][8][128];
    const int tid = threadIdx.x;
    const int bx = blockIdx.x;   // j tile
    const int by = blockIdx.y;   // i tile
    const int bh = blockIdx.z;
    const int b = bh >> 3, h = bh & 7;
    const int tx = tid & 15, ty = tid >> 4;
    const int lane = tid & 31;
    const int lr = tid >> 1, lc = (tid & 1) * 4;

    const float* qbase = g_qkv + (size_t)b * NSEQ * QKVN + h * DHEAD;
    const float* qp = qbase + (size_t)(by * 128 + lr) * QKVN + lc;
    const float* kp = qbase + INNER + (size_t)(bx * 128 + lr) * QKVN + lc;

    float4 q4 = *(const float4*)qp;
    float4 k4 = *(const float4*)kp;
    Qs[0][lc + 0][lr] = q4.x; Qs[0][lc + 1][lr] = q4.y;
    Qs[0][lc + 2][lr] = q4.z; Qs[0][lc + 3][lr] = q4.w;
    Ks[0][lc + 0][lr] = k4.x; Ks[0][lc + 1][lr] = k4.y;
    Ks[0][lc + 2][lr] = k4.z; Ks[0][lc + 3][lr] = k4.w;
    __syncthreads();

    float acc[8][8] = {};
    int cur = 0;
    for (int d0 = 0; d0 < DHEAD; d0 += 8) {
        const bool nxt = (d0 + 8 < DHEAD);
        if (nxt) {
            q4 = *(const float4*)(qp + d0 + 8);
            k4 = *(const float4*)(kp + d0 + 8);
        }
        #pragma unroll
        for (int kk = 0; kk < 8; kk++) {
            float ar[8], br[8];
            #pragma unroll
            for (int i = 0; i < 8; i++) ar[i] = Qs[cur][kk][ty * 8 + i];
            #pragma unroll
            for (int j = 0; j < 8; j++) br[j] = Ks[cur][kk][tx * 8 + j];
            #pragma unroll
            for (int i = 0; i < 8; i++)
                #pragma unroll
                for (int j = 0; j < 8; j++)
                    acc[i][j] = fmaf(ar[i], br[j], acc[i][j]);
        }
        if (nxt) {
            int b2 = cur ^ 1;
            Qs[b2][lc + 0][lr] = q4.x; Qs[b2][lc + 1][lr] = q4.y;
            Qs[b2][lc + 2][lr] = q4.z; Qs[b2][lc + 3][lr] = q4.w;
            Ks[b2][lc + 0][lr] = k4.x; Ks[b2][lc + 1][lr] = k4.y;
            Ks[b2][lc + 2][lr] = k4.z; Ks[b2][lc + 3][lr] = k4.w;
            __syncthreads();
            cur = b2;
        }
    }

    // Epilogue: stats + warp-aggregated candidate push (no score store)
    #pragma unroll
    for (int i = 0; i < 8; i++) {
        float z[8];
        #pragma unroll
        for (int j = 0; j < 8; j++) z[j] = acc[i][j] * SCALE;

        // per-(row, jtile) stats: 16 lanes sharing ty reduce over 128 cols
        float m = z[0];
        #pragma unroll
        for (int j = 1; j < 8; j++) m = fmaxf(m, z[j]);
        #pragma unroll
        for (int o = 8; o > 0; o >>= 1)
            m = fmaxf(m, __shfl_xor_sync(0xffffffffu, m, o));
        float s = 0.0f;
        #pragma unroll
        for (int j = 0; j < 8; j++) s += __expf(z[j] - m);
        #pragma unroll
        for (int o = 8; o > 0; o >>= 1)
            s += __shfl_xor_sync(0xffffffffu, s, o);

        size_t row = (size_t)bh * NSEQ + by * 128 + ty * 8 + i;
        if (tx == 0) g_part[row * 16 + bx] = make_float2(m, s);

        // conservative per-tile candidate cutoff (lower bound on global cutoff)
        float zcut = m + __logf(THRESH * s) - 1e-3f;
        int flags = 0;
        #pragma unroll
        for (int j = 0; j < 8; j++)
            if (z[j] > zcut) flags |= 1 << j;
        int cnt = __popc(flags);

        // inclusive prefix sum over the 16-lane row group
        int pre = cnt;
        #pragma unroll
        for (int o = 1; o <= 8; o <<= 1) {
            int v = __shfl_up_sync(0xffffffffu, pre, o);
            if ((lane & 15) >= o) pre += v;
        }
        int total = __shfl_sync(0xffffffffu, pre, lane | 15);
        int base = 0;
        if ((lane & 15) == 15 && total > 0)
            base = atomicAdd(&g_ccnt[row], total);
        base = __shfl_sync(0xffffffffu, base, lane | 15);

        int off = base + pre - cnt;   // exclusive prefix
        #pragma unroll
        for (int j = 0; j < 8; j++) {
            if ((flags >> j) & 1) {
                if (off < MAXC)
                    g_cand[row * MAXC + off] =
                        make_int2(bx * 128 + tx * 8 + j, __float_as_int(z[j]));
                off++;
            }
        }
    }
}

// ---------------------------------------------------------------------------
// Fused select + sparse PV: one warp per attention row.
// Combine 16 partials -> exact (m, Z) (R7 semantics). Lane-parallel candidate
// evaluation (32 exps per warp-instruction), ballot, then warp-cooperative
// V accumulation for the ~0.45 survivors/row. Decision arithmetic identical
// to R7: p = __expf(z - m) * inv > THRESH on the fp32 z from scores_kernel.
// ---------------------------------------------------------------------------
__global__ __launch_bounds__(256) void ctx_kernel()
{
    const size_t w = ((size_t)blockIdx.x * blockDim.x + threadIdx.x) >> 5;
    const int lane = threadIdx.x & 31;
    if (w >= NROWS) return;
    const int bh = (int)(w >> 11), i = (int)(w & 2047);
    const int b = bh >> 3, h = bh & 7;

    // combine per-tile partials (warp all-reduce; zeros from lanes 16-31 are exact)
    float2 pk = (lane < 16) ? g_part[w * 16 + lane] : make_float2(-1e30f, 0.0f);
    float m = pk.x;
    #pragma unroll
    for (int o = 16; o > 0; o >>= 1)
        m = fmaxf(m, __shfl_xor_sync(0xffffffffu, m, o));
    float e = (lane < 16) ? pk.y * __expf(pk.x - m) : 0.0f;
    #pragma unroll
    for (int o = 16; o > 0; o >>= 1)
        e += __shfl_xor_sync(0xffffffffu, e, o);
    const float inv = 1.0f / e;

    int n = g_ccnt[w];
    if (n > MAXC) n = MAXC;
    const int2* cp = g_cand + w * MAXC;
    const float* Vb = g_qkv + (size_t)b * NSEQ * QKVN + 2 * INNER + h * DHEAD;

    float a0 = 0.0f, a1 = 0.0f;
    for (int c0 = 0; c0 < n; c0 += 32) {
        int idx = c0 + lane;
        int2 cd = (idx < n) ? cp[idx] : make_int2(0, (int)0xff800000u);  // z = -inf
        float pv = __expf(__int_as_float(cd.y) - m) * inv;
        unsigned bal = __ballot_sync(0xffffffffu, pv > THRESH);
        while (bal) {
            int src = __ffs(bal) - 1;
            bal &= bal - 1;
            float pvs = __shfl_sync(0xffffffffu, pv, src);
            int   col = __shfl_sync(0xffffffffu, cd.x, src);
            const float* v = Vb + (size_t)col * QKVN;
            a0 = fmaf(pvs, v[lane],      a0);
            a1 = fmaf(pvs, v[lane + 32], a1);
        }
    }
    float* o = g_ctx + ((size_t)b * NSEQ + i) * INNER + h * DHEAD;
    o[lane]      = a0;
    o[lane + 32] = a1;
}

// ---------------------------------------------------------------------------
// 3xTF32 helpers (smooth path)
// ---------------------------------------------------------------------------
__device__ __forceinline__ void split_tf32(float x, uint32_t& hi, uint32_t& lo) {
    uint32_t h;
    asm("cvt.rna.tf32.f32 %0, %1;" : "=r"(h) : "f"(x));
    float hf = __uint_as_float(h);
    asm("cvt.rna.tf32.f32 %0, %1;" : "=r"(lo) : "f"(x - hf));
    hi = h;
}
__device__ __forceinline__ void mma8(float* c, const uint32_t* a, const uint32_t* b) {
    asm volatile(
        "mma.sync.aligned.m16n8k8.row.col.f32.tf32.tf32.f32 "
        "{%0,%1,%2,%3},{%4,%5,%6,%7},{%8,%9},{%0,%1,%2,%3};"
        : "+f"(c[0]), "+f"(c[1]), "+f"(c[2]), "+f"(c[3])
        : "r"(a[0]), "r"(a[1]), "r"(a[2]), "r"(a[3]), "r"(b[0]), "r"(b[1]));
}
__device__ __forceinline__ void mma3(float* c, const uint32_t* ah, const uint32_t* al,
                                     const uint32_t* bh, const uint32_t* bl) {
    mma8(c, ah, bh);
    mma8(c, ah, bl);
    mma8(c, al, bh);
}

// ---------------------------------------------------------------------------
// Out-proj (3-term tf32, smooth path): C = A @ B + bias  (validated R4-R7)
// ---------------------------------------------------------------------------
__global__ __launch_bounds__(256) void sgemm_mma_bias(
    const float* __restrict__ A, const float* __restrict__ Bm,
    const float* __restrict__ bias, float* __restrict__ C,
    int M, int N, int K)
{
    __shared__ uint32_t As[2][16][136];
    __shared__ uint32_t Bs[2][16][136];
    const int tid = threadIdx.x;
    const int bx = blockIdx.x, by = blockIdx.y;
    const int lane = tid & 31, wid = tid >> 5;
    const int gid = lane >> 2, tig = lane & 3;
    const int wm = wid & 1, wn = wid >> 1;
    const int ar = tid >> 2, aq = tid & 3;
    const int bkr = tid >> 4, bc = (tid & 15) * 8;

    const float* Ap0 = A + (size_t)(by * 128 + ar) * K + aq * 4;
    const float* Ap1 = Ap0 + (size_t)64 * K;
    const float* Bp  = Bm + (size_t)bkr * N + bx * 128 + bc;

    float4 av0 = *(const float4*)Ap0;
    float4 av1 = *(const float4*)Ap1;
    float4 bv0 = *(const float4*)Bp;
    float4 bv1 = *(const float4*)(Bp + 4);

    float acc[4][4][4] = {};

    for (int k0 = 0; k0 < K; k0 += 16) {
        const float* a0 = &av0.x; const float* a1 = &av1.x;
        #pragma unroll
        for (int e = 0; e < 4; e++) {
            uint32_t h, l;
            split_tf32(a0[e], h, l);
            As[0][aq * 4 + e][ar] = h; As[1][aq * 4 + e][ar] = l;
            split_tf32(a1[e], h, l);
            As[0][aq * 4 + e][ar + 64] = h; As[1][aq * 4 + e][ar + 64] = l;
        }
        const float* b0p = &bv0.x; const float* b1p = &bv1.x;
        #pragma unroll
        for (int e = 0; e < 4; e++) {
            uint32_t h, l;
            split_tf32(b0p[e], h, l);
            Bs[0][bkr][bc + e] = h; Bs[1][bkr][bc + e] = l;
            split_tf32(b1p[e], h, l);
            Bs[0][bkr][bc + 4 + e] = h; Bs[1][bkr][bc + 4 + e] = l;
        }
        __syncthreads();

        if (k0 + 16 < K) {
            av0 = *(const float4*)(Ap0 + k0 + 16);
            av1 = *(const float4*)(Ap1 + k0 + 16);
            bv0 = *(const float4*)(Bp + (size_t)(k0 + 16) * N);
            bv1 = *(const float4*)(Bp + (size_t)(k0 + 16) * N + 4);
        }

        #pragma unroll
        for (int ks = 0; ks < 16; ks += 8) {
            uint32_t afh[4][4], afl[4][4], bfh[4][2], bfl[4][2];
            #pragma unroll
            for (int i = 0; i < 4; i++) {
                int m0 = wm * 64 + i * 16;
                afh[i][0] = As[0][ks + tig][m0 + gid];
                afh[i][1] = As[0][ks + tig][m0 + gid + 8];
                afh[i][2] = As[0][ks + tig + 4][m0 + gid];
                afh[i][3] = As[0][ks + tig + 4][m0 + gid + 8];
                afl[i][0] = As[1][ks + tig][m0 + gid];
                afl[i][1] = As[1][ks + tig][m0 + gid + 8];
                afl[i][2] = As[1][ks + tig + 4][m0 + gid];
                afl[i][3] = As[1][ks + tig + 4][m0 + gid + 8];
            }
            #pragma unroll
            for (int j = 0; j < 4; j++) {
                int n0 = wn * 32 + j * 8;
                bfh[j][0] = Bs[0][ks + tig][n0 + gid];
                bfh[j][1] = Bs[0][ks + tig + 4][n0 + gid];
                bfl[j][0] = Bs[1][ks + tig][n0 + gid];
                bfl[j][1] = Bs[1][ks + tig + 4][n0 + gid];
            }
            #pragma unroll
            for (int i = 0; i < 4; i++)
                #pragma unroll
                for (int j = 0; j < 4; j++)
                    mma3(acc[i][j], afh[i], afl[i], bfh[j], bfl[j]);
        }
        __syncthreads();
    }

    #pragma unroll
    for (int i = 0; i < 4; i++) {
        int row = by * 128 + wm * 64 + i * 16 + gid;
        #pragma unroll
        for (int j = 0; j < 4; j++) {
            int col = bx * 128 + wn * 32 + j * 8 + tig * 2;
            float b0 = bias ? bias[col] : 0.f;
            float b1 = bias ? bias[col + 1] : 0.f;
            *(float2*)(C + (size_t)row * N + col) =
                make_float2(acc[i][j][0] + b0, acc[i][j][1] + b1);
            *(float2*)(C + (size_t)(row + 8) * N + col) =
                make_float2(acc[i][j][2] + b0, acc[i][j][3] + b1);
        }
    }
}

// ---------------------------------------------------------------------------
extern "C" void kernel_launch(void* const* d_in, const int* in_sizes, int n_in,
                              void* d_out, int out_size)
{
    const float* x    = (const float*)d_in[0];
    const float* Wqkv = (const float*)d_in[1];
    const float* bqkv = (const float*)d_in[2];
    const float* Wout = (const float*)d_in[3];
    const float* bout = (const float*)d_in[4];
    float* out = (float*)d_out;

    float *qkv_ptr, *ctx_ptr;
    int* ccnt_ptr;
    cudaGetSymbolAddress((void**)&qkv_ptr,  g_qkv);
    cudaGetSymbolAddress((void**)&ctx_ptr,  g_ctx);
    cudaGetSymbolAddress((void**)&ccnt_ptr, g_ccnt);

    // 0) Zero candidate counters (graph-capturable async memset)
    cudaMemsetAsync(ccnt_ptr, 0, NROWS * sizeof(int));

    // 1) QKV projection (fp32, decision-critical, double-buffered)
    sgemm_bias_kernel<<<dim3(QKVN / 128, (BATCH * NSEQ) / 128), 256>>>(
        x, Wqkv, bqkv, qkv_ptr, BATCH * NSEQ, QKVN, DIM);

    // 2) Attention scores (fp32) -> per-tile stats + candidate list ONLY
    //    (no 537 MB score tensor; ~466 candidates/row, MAXC bound is provable)
    scores_kernel<<<dim3(NSEQ / 128, NSEQ / 128, BATCH * HEADS), 256>>>();

    // 3) Fused exact-softmax decision + sparse P@V (one warp per row)
    ctx_kernel<<<(int)(NROWS * 32 / 256), 256>>>();

    // 4) Output projection (3-term tf32 tensor path)
    sgemm_mma_bias<<<dim3(INNER / 128, (BATCH * NSEQ) / 128), 256>>>(
        ctx_ptr, Wout, bout, out, BATCH * NSEQ, INNER, INNER);
}

// round 15
// speedup vs baseline: 1.0014x; 1.0014x over previous
#include <cuda_runtime.h>
#include <cstdint>

// Problem constants
#define BATCH   4
#define NSEQ    2048
#define DIM     512
#define HEADS   8
#define DHEAD   64
#define INNER   512          // HEADS*DHEAD
#define QKVN    1536         // 3*INNER
#define SCALE   0.125f       // 64^-0.5
#define THRESH  0.01f
#define NROWS   ((size_t)BATCH * HEADS * NSEQ)   // 65536 attention rows
#define MAXC    1664   // hard bound: <=100 candidates/tile (each >1% of tile sum) * 16 tiles

// Scratch (device globals: allocation-free per harness rules)
__device__ float  g_qkv[(size_t)BATCH * NSEQ * QKVN];                // 50.3 MB
__device__ float  g_ctx[(size_t)BATCH * NSEQ * INNER];               // 16.8 MB
__device__ float2 g_part[NROWS * 16];                                // (max, sumexp) per (row, jtile)
__device__ int    g_ccnt[NROWS];                                     // candidate counts
__device__ int2   g_cand[NROWS * MAXC];                              // (col, z as bits) ~873 MB

// ---------------------------------------------------------------------------
// fp32 SGEMM, double-buffered (decision-critical): C = A @ B + bias
// 128x128 tile, BK=8, 256 threads, 8x8 per thread. (validated R7)
// ---------------------------------------------------------------------------
__global__ __launch_bounds__(256) void sgemm_bias_kernel(
    const float* __restrict__ A, const float* __restrict__ Bm,
    const float* __restrict__ bias, float* __restrict__ C,
    int M, int Nn, int K)
{
    __shared__ float As[2][8][128];
    __shared__ float Bs[2][8][128];
    const int tid = threadIdx.x;
    const int bx = blockIdx.x, by = blockIdx.y;
    const int tx = tid & 15, ty = tid >> 4;
    const int la_r = tid >> 1, la_c = (tid & 1) * 4;
    const int lb_r = tid >> 5, lb_c = (tid & 31) * 4;

    const float* Ap = A + (size_t)(by * 128 + la_r) * K + la_c;
    const float* Bp = Bm + (size_t)lb_r * Nn + bx * 128 + lb_c;

    float4 a4 = *(const float4*)Ap;
    float4 b4 = *(const float4*)Bp;
    As[0][la_c + 0][la_r] = a4.x; As[0][la_c + 1][la_r] = a4.y;
    As[0][la_c + 2][la_r] = a4.z; As[0][la_c + 3][la_r] = a4.w;
    *(float4*)&Bs[0][lb_r][lb_c] = b4;
    __syncthreads();

    float acc[8][8] = {};
    int cur = 0;
    for (int k0 = 0; k0 < K; k0 += 8) {
        const bool nxt = (k0 + 8 < K);
        if (nxt) {
            a4 = *(const float4*)(Ap + k0 + 8);
            b4 = *(const float4*)(Bp + (size_t)(k0 + 8) * Nn);
        }
        #pragma unroll
        for (int kk = 0; kk < 8; kk++) {
            float ar[8], br[8];
            #pragma unroll
            for (int i = 0; i < 8; i++) ar[i] = As[cur][kk][ty * 8 + i];
            #pragma unroll
            for (int j = 0; j < 8; j++) br[j] = Bs[cur][kk][tx * 8 + j];
            #pragma unroll
            for (int i = 0; i < 8; i++)
                #pragma unroll
                for (int j = 0; j < 8; j++)
                    acc[i][j] = fmaf(ar[i], br[j], acc[i][j]);
        }
        if (nxt) {
            int b2 = cur ^ 1;
            As[b2][la_c + 0][la_r] = a4.x; As[b2][la_c + 1][la_r] = a4.y;
            As[b2][la_c + 2][la_r] = a4.z; As[b2][la_c + 3][la_r] = a4.w;
            *(float4*)&Bs[b2][lb_r][lb_c] = b4;
            __syncthreads();
            cur = b2;
        }
    }

    float bv[8];
    #pragma unroll
    for (int j = 0; j < 8; j++) bv[j] = bias ? bias[bx * 128 + tx * 8 + j] : 0.0f;
    #pragma unroll
    for (int i = 0; i < 8; i++) {
        size_t roff = (size_t)(by * 128 + ty * 8 + i) * Nn + bx * 128 + tx * 8;
        float4 o0 = make_float4(acc[i][0] + bv[0], acc[i][1] + bv[1],
                                acc[i][2] + bv[2], acc[i][3] + bv[3]);
        float4 o1 = make_float4(acc[i][4] + bv[4], acc[i][5] + bv[5],
                                acc[i][6] + bv[6], acc[i][7] + bv[7]);
        *(float4*)(C + roff)     = o0;
        *(float4*)(C + roff + 4) = o1;
    }
}

// ---------------------------------------------------------------------------
// fp32 scores (decision-critical), double-buffered. NO score tensor output.
// Epilogue: per-(row, jtile) stats (m, sumexp) -> g_part, and candidate push
// with per-tile cutoff zcut = m_t + ln(THRESH*s_t) - 1e-3 (provable superset
// of global survivors; <=100/tile by construction so MAXC=1664 never
// overflows). Push is warp-aggregated: one atomicAdd per (row, tile).
// ---------------------------------------------------------------------------
__global__ __launch_bounds__(256) void scores_kernel()
{
    __shared__ float Qs[2][8][128];
    __shared__ float Ks[2][8][128];
    const int tid = threadIdx.x;
    const int bx = blockIdx.x;   // j tile
    const int by = blockIdx.y;   // i tile
    const int bh = blockIdx.z;
    const int b = bh >> 3, h = bh & 7;
    const int tx = tid & 15, ty = tid >> 4;
    const int lane = tid & 31;
    const int lr = tid >> 1, lc = (tid & 1) * 4;

    const float* qbase = g_qkv + (size_t)b * NSEQ * QKVN + h * DHEAD;
    const float* qp = qbase + (size_t)(by * 128 + lr) * QKVN + lc;
    const float* kp = qbase + INNER + (size_t)(bx * 128 + lr) * QKVN + lc;

    float4 q4 = *(const float4*)qp;
    float4 k4 = *(const float4*)kp;
    Qs[0][lc + 0][lr] = q4.x; Qs[0][lc + 1][lr] = q4.y;
    Qs[0][lc + 2][lr] = q4.z; Qs[0][lc + 3][lr] = q4.w;
    Ks[0][lc + 0][lr] = k4.x; Ks[0][lc + 1][lr] = k4.y;
    Ks[0][lc + 2][lr] = k4.z; Ks[0][lc + 3][lr] = k4.w;
    __syncthreads();

    float acc[8][8] = {};
    int cur = 0;
    for (int d0 = 0; d0 < DHEAD; d0 += 8) {
        const bool nxt = (d0 + 8 < DHEAD);
        if (nxt) {
            q4 = *(const float4*)(qp + d0 + 8);
            k4 = *(const float4*)(kp + d0 + 8);
        }
        #pragma unroll
        for (int kk = 0; kk < 8; kk++) {
            float ar[8], br[8];
            #pragma unroll
            for (int i = 0; i < 8; i++) ar[i] = Qs[cur][kk][ty * 8 + i];
            #pragma unroll
            for (int j = 0; j < 8; j++) br[j] = Ks[cur][kk][tx * 8 + j];
            #pragma unroll
            for (int i = 0; i < 8; i++)
                #pragma unroll
                for (int j = 0; j < 8; j++)
                    acc[i][j] = fmaf(ar[i], br[j], acc[i][j]);
        }
        if (nxt) {
            int b2 = cur ^ 1;
            Qs[b2][lc + 0][lr] = q4.x; Qs[b2][lc + 1][lr] = q4.y;
            Qs[b2][lc + 2][lr] = q4.z; Qs[b2][lc + 3][lr] = q4.w;
            Ks[b2][lc + 0][lr] = k4.x; Ks[b2][lc + 1][lr] = k4.y;
            Ks[b2][lc + 2][lr] = k4.z; Ks[b2][lc + 3][lr] = k4.w;
            __syncthreads();
            cur = b2;
        }
    }

    // Epilogue: stats + warp-aggregated candidate push (no score store)
    #pragma unroll
    for (int i = 0; i < 8; i++) {
        float z[8];
        #pragma unroll
        for (int j = 0; j < 8; j++) z[j] = acc[i][j] * SCALE;

        // per-(row, jtile) stats: 16 lanes sharing ty reduce over 128 cols
        float m = z[0];
        #pragma unroll
        for (int j = 1; j < 8; j++) m = fmaxf(m, z[j]);
        #pragma unroll
        for (int o = 8; o > 0; o >>= 1)
            m = fmaxf(m, __shfl_xor_sync(0xffffffffu, m, o));
        float s = 0.0f;
        #pragma unroll
        for (int j = 0; j < 8; j++) s += __expf(z[j] - m);
        #pragma unroll
        for (int o = 8; o > 0; o >>= 1)
            s += __shfl_xor_sync(0xffffffffu, s, o);

        size_t row = (size_t)bh * NSEQ + by * 128 + ty * 8 + i;
        if (tx == 0) g_part[row * 16 + bx] = make_float2(m, s);

        // conservative per-tile candidate cutoff (lower bound on global cutoff)
        float zcut = m + __logf(THRESH * s) - 1e-3f;
        int flags = 0;
        #pragma unroll
        for (int j = 0; j < 8; j++)
            if (z[j] > zcut) flags |= 1 << j;
        int cnt = __popc(flags);

        // inclusive prefix sum over the 16-lane row group
        int pre = cnt;
        #pragma unroll
        for (int o = 1; o <= 8; o <<= 1) {
            int v = __shfl_up_sync(0xffffffffu, pre, o);
            if ((lane & 15) >= o) pre += v;
        }
        int total = __shfl_sync(0xffffffffu, pre, lane | 15);
        int base = 0;
        if ((lane & 15) == 15 && total > 0)
            base = atomicAdd(&g_ccnt[row], total);
        base = __shfl_sync(0xffffffffu, base, lane | 15);

        int off = base + pre - cnt;   // exclusive prefix
        #pragma unroll
        for (int j = 0; j < 8; j++) {
            if ((flags >> j) & 1) {
                if (off < MAXC)
                    g_cand[row * MAXC + off] =
                        make_int2(bx * 128 + tx * 8 + j, __float_as_int(z[j]));
                off++;
            }
        }
    }
}

// ---------------------------------------------------------------------------
// Fused select + sparse PV: one warp per attention row.
// Combine 16 partials -> exact (m, Z) (R7 semantics). Lane-parallel candidate
// evaluation (32 exps per warp-instruction), ballot, then warp-cooperative
// V accumulation for the ~0.45 survivors/row. Decision arithmetic identical
// to R7: p = __expf(z - m) * inv > THRESH on the fp32 z from scores_kernel.
// ---------------------------------------------------------------------------
__global__ __launch_bounds__(256) void ctx_kernel()
{
    const size_t w = ((size_t)blockIdx.x * blockDim.x + threadIdx.x) >> 5;
    const int lane = threadIdx.x & 31;
    if (w >= NROWS) return;
    const int bh = (int)(w >> 11), i = (int)(w & 2047);
    const int b = bh >> 3, h = bh & 7;

    // combine per-tile partials (warp all-reduce; zeros from lanes 16-31 are exact)
    float2 pk = (lane < 16) ? g_part[w * 16 + lane] : make_float2(-1e30f, 0.0f);
    float m = pk.x;
    #pragma unroll
    for (int o = 16; o > 0; o >>= 1)
        m = fmaxf(m, __shfl_xor_sync(0xffffffffu, m, o));
    float e = (lane < 16) ? pk.y * __expf(pk.x - m) : 0.0f;
    #pragma unroll
    for (int o = 16; o > 0; o >>= 1)
        e += __shfl_xor_sync(0xffffffffu, e, o);
    const float inv = 1.0f / e;

    int n = g_ccnt[w];
    if (n > MAXC) n = MAXC;
    const int2* cp = g_cand + w * MAXC;
    const float* Vb = g_qkv + (size_t)b * NSEQ * QKVN + 2 * INNER + h * DHEAD;

    float a0 = 0.0f, a1 = 0.0f;
    for (int c0 = 0; c0 < n; c0 += 32) {
        int idx = c0 + lane;
        int2 cd = (idx < n) ? cp[idx] : make_int2(0, (int)0xff800000u);  // z = -inf
        float pv = __expf(__int_as_float(cd.y) - m) * inv;
        unsigned bal = __ballot_sync(0xffffffffu, pv > THRESH);
        while (bal) {
            int src = __ffs(bal) - 1;
            bal &= bal - 1;
            float pvs = __shfl_sync(0xffffffffu, pv, src);
            int   col = __shfl_sync(0xffffffffu, cd.x, src);
            const float* v = Vb + (size_t)col * QKVN;
            a0 = fmaf(pvs, v[lane],      a0);
            a1 = fmaf(pvs, v[lane + 32], a1);
        }
    }
    float* o = g_ctx + ((size_t)b * NSEQ + i) * INNER + h * DHEAD;
    o[lane]      = a0;
    o[lane + 32] = a1;
}

// ---------------------------------------------------------------------------
// 3xTF32 helpers (smooth path)
// ---------------------------------------------------------------------------
__device__ __forceinline__ void split_tf32(float x, uint32_t& hi, uint32_t& lo) {
    uint32_t h;
    asm("cvt.rna.tf32.f32 %0, %1;" : "=r"(h) : "f"(x));
    float hf = __uint_as_float(h);
    asm("cvt.rna.tf32.f32 %0, %1;" : "=r"(lo) : "f"(x - hf));
    hi = h;
}
__device__ __forceinline__ void mma8(float* c, const uint32_t* a, const uint32_t* b) {
    asm volatile(
        "mma.sync.aligned.m16n8k8.row.col.f32.tf32.tf32.f32 "
        "{%0,%1,%2,%3},{%4,%5,%6,%7},{%8,%9},{%0,%1,%2,%3};"
        : "+f"(c[0]), "+f"(c[1]), "+f"(c[2]), "+f"(c[3])
        : "r"(a[0]), "r"(a[1]), "r"(a[2]), "r"(a[3]), "r"(b[0]), "r"(b[1]));
}
__device__ __forceinline__ void mma3(float* c, const uint32_t* ah, const uint32_t* al,
                                     const uint32_t* bh, const uint32_t* bl) {
    mma8(c, ah, bh);
    mma8(c, ah, bl);
    mma8(c, al, bh);
}

// ---------------------------------------------------------------------------
// Out-proj (3-term tf32, smooth path): C = A @ B + bias  (validated R4-R7)
// ---------------------------------------------------------------------------
__global__ __launch_bounds__(256) void sgemm_mma_bias(
    const float* __restrict__ A, const float* __restrict__ Bm,
    const float* __restrict__ bias, float* __restrict__ C,
    int M, int N, int K)
{
    __shared__ uint32_t As[2][16][136];
    __shared__ uint32_t Bs[2][16][136];
    const int tid = threadIdx.x;
    const int bx = blockIdx.x, by = blockIdx.y;
    const int lane = tid & 31, wid = tid >> 5;
    const int gid = lane >> 2, tig = lane & 3;
    const int wm = wid & 1, wn = wid >> 1;
    const int ar = tid >> 2, aq = tid & 3;
    const int bkr = tid >> 4, bc = (tid & 15) * 8;

    const float* Ap0 = A + (size_t)(by * 128 + ar) * K + aq * 4;
    const float* Ap1 = Ap0 + (size_t)64 * K;
    const float* Bp  = Bm + (size_t)bkr * N + bx * 128 + bc;

    float4 av0 = *(const float4*)Ap0;
    float4 av1 = *(const float4*)Ap1;
    float4 bv0 = *(const float4*)Bp;
    float4 bv1 = *(const float4*)(Bp + 4);

    float acc[4][4][4] = {};

    for (int k0 = 0; k0 < K; k0 += 16) {
        const float* a0 = &av0.x; const float* a1 = &av1.x;
        #pragma unroll
        for (int e = 0; e < 4; e++) {
            uint32_t h, l;
            split_tf32(a0[e], h, l);
            As[0][aq * 4 + e][ar] = h; As[1][aq * 4 + e][ar] = l;
            split_tf32(a1[e], h, l);
            As[0][aq * 4 + e][ar + 64] = h; As[1][aq * 4 + e][ar + 64] = l;
        }
        const float* b0p = &bv0.x; const float* b1p = &bv1.x;
        #pragma unroll
        for (int e = 0; e < 4; e++) {
            uint32_t h, l;
            split_tf32(b0p[e], h, l);
            Bs[0][bkr][bc + e] = h; Bs[1][bkr][bc + e] = l;
            split_tf32(b1p[e], h, l);
            Bs[0][bkr][bc + 4 + e] = h; Bs[1][bkr][bc + 4 + e] = l;
        }
        __syncthreads();

        if (k0 + 16 < K) {
            av0 = *(const float4*)(Ap0 + k0 + 16);
            av1 = *(const float4*)(Ap1 + k0 + 16);
            bv0 = *(const float4*)(Bp + (size_t)(k0 + 16) * N);
            bv1 = *(const float4*)(Bp + (size_t)(k0 + 16) * N + 4);
        }

        #pragma unroll
        for (int ks = 0; ks < 16; ks += 8) {
            uint32_t afh[4][4], afl[4][4], bfh[4][2], bfl[4][2];
            #pragma unroll
            for (int i = 0; i < 4; i++) {
                int m0 = wm * 64 + i * 16;
                afh[i][0] = As[0][ks + tig][m0 + gid];
                afh[i][1] = As[0][ks + tig][m0 + gid + 8];
                afh[i][2] = As[0][ks + tig + 4][m0 + gid];
                afh[i][3] = As[0][ks + tig + 4][m0 + gid + 8];
                afl[i][0] = As[1][ks + tig][m0 + gid];
                afl[i][1] = As[1][ks + tig][m0 + gid + 8];
                afl[i][2] = As[1][ks + tig + 4][m0 + gid];
                afl[i][3] = As[1][ks + tig + 4][m0 + gid + 8];
            }
            #pragma unroll
            for (int j = 0; j < 4; j++) {
                int n0 = wn * 32 + j * 8;
                bfh[j][0] = Bs[0][ks + tig][n0 + gid];
                bfh[j][1] = Bs[0][ks + tig + 4][n0 + gid];
                bfl[j][0] = Bs[1][ks + tig][n0 + gid];
                bfl[j][1] = Bs[1][ks + tig + 4][n0 + gid];
            }
            #pragma unroll
            for (int i = 0; i < 4; i++)
                #pragma unroll
                for (int j = 0; j < 4; j++)
                    mma3(acc[i][j], afh[i], afl[i], bfh[j], bfl[j]);
        }
        __syncthreads();
    }

    #pragma unroll
    for (int i = 0; i < 4; i++) {
        int row = by * 128 + wm * 64 + i * 16 + gid;
        #pragma unroll
        for (int j = 0; j < 4; j++) {
            int col = bx * 128 + wn * 32 + j * 8 + tig * 2;
            float b0 = bias ? bias[col] : 0.f;
            float b1 = bias ? bias[col + 1] : 0.f;
            *(float2*)(C + (size_t)row * N + col) =
                make_float2(acc[i][j][0] + b0, acc[i][j][1] + b1);
            *(float2*)(C + (size_t)(row + 8) * N + col) =
                make_float2(acc[i][j][2] + b0, acc[i][j][3] + b1);
        }
    }
}

// ---------------------------------------------------------------------------
extern "C" void kernel_launch(void* const* d_in, const int* in_sizes, int n_in,
                              void* d_out, int out_size)
{
    const float* x    = (const float*)d_in[0];
    const float* Wqkv = (const float*)d_in[1];
    const float* bqkv = (const float*)d_in[2];
    const float* Wout = (const float*)d_in[3];
    const float* bout = (const float*)d_in[4];
    float* out = (float*)d_out;

    float *qkv_ptr, *ctx_ptr;
    int* ccnt_ptr;
    cudaGetSymbolAddress((void**)&qkv_ptr,  g_qkv);
    cudaGetSymbolAddress((void**)&ctx_ptr,  g_ctx);
    cudaGetSymbolAddress((void**)&ccnt_ptr, g_ccnt);

    // 0) Zero candidate counters (graph-capturable async memset)
    cudaMemsetAsync(ccnt_ptr, 0, NROWS * sizeof(int));

    // 1) QKV projection (fp32, decision-critical, double-buffered)
    sgemm_bias_kernel<<<dim3(QKVN / 128, (BATCH * NSEQ) / 128), 256>>>(
        x, Wqkv, bqkv, qkv_ptr, BATCH * NSEQ, QKVN, DIM);

    // 2) Attention scores (fp32) -> per-tile stats + candidate list ONLY
    //    (no 537 MB score tensor; ~466 candidates/row, MAXC bound is provable)
    scores_kernel<<<dim3(NSEQ / 128, NSEQ / 128, BATCH * HEADS), 256>>>();

    // 3) Fused exact-softmax decision + sparse P@V (one warp per row)
    ctx_kernel<<<(int)(NROWS * 32 / 256), 256>>>();

    // 4) Output projection (3-term tf32 tensor path)
    sgemm_mma_bias<<<dim3(INNER / 128, (BATCH * NSEQ) / 128), 256>>>(
        ctx_ptr, Wout, bout, out, BATCH * NSEQ, INNER, INNER);
}